// round 2
// baseline (speedup 1.0000x reference)
#include <cuda_runtime.h>
#include <math.h>

#define BB 2
#define SS 2048
#define DD 1024
#define HH 16
#define HD 64
#define MROWS (BB*SS)   // 4096

// ---------------- scratch (no allocations allowed) ----------------
__device__ float g_q[BB*HH*SS*HD];    // [B,H,S,HD]
__device__ float g_k[BB*HH*SS*HD];
__device__ float g_v[BB*HH*SS*HD];
__device__ float g_ctx[BB*SS*DD];     // [B,S,D]

// ---------------- GEMM: out = A[M,K] @ W[K,N] + bias[N] ----------------
// HEADS=1: write in [B,H,S,HD] layout (n -> h,hd ; m -> b,s)
// HEADS=0: write flat [M,N]
template<int HEADS>
__global__ __launch_bounds__(256)
void gemm64(const float* __restrict__ A, const float* __restrict__ W,
            const float* __restrict__ bias, float* __restrict__ out,
            int M, int N, int K)
{
    __shared__ float As[16][64];   // As[k][m]
    __shared__ float Ws[16][64];   // Ws[k][n]

    const int tid = threadIdx.x;
    const int tx = tid & 15, ty = tid >> 4;
    const int m0 = blockIdx.y * 64, n0 = blockIdx.x * 64;

    float acc[4][4] = {};

    const int arow = tid >> 2;          // 0..63
    const int ak4  = (tid & 3) * 4;     // 0,4,8,12
    const int wrow = tid >> 4;          // 0..15
    const int wc4  = (tid & 15) * 4;    // 0..60

    for (int k0 = 0; k0 < K; k0 += 16) {
        float4 av = *(const float4*)&A[(size_t)(m0 + arow) * K + k0 + ak4];
        As[ak4 + 0][arow] = av.x;
        As[ak4 + 1][arow] = av.y;
        As[ak4 + 2][arow] = av.z;
        As[ak4 + 3][arow] = av.w;
        float4 wv = *(const float4*)&W[(size_t)(k0 + wrow) * N + n0 + wc4];
        *(float4*)&Ws[wrow][wc4] = wv;
        __syncthreads();

        #pragma unroll
        for (int kk = 0; kk < 16; kk++) {
            float4 a = *(const float4*)&As[kk][ty * 4];
            float4 b = *(const float4*)&Ws[kk][tx * 4];
            float ar[4] = {a.x, a.y, a.z, a.w};
            float br[4] = {b.x, b.y, b.z, b.w};
            #pragma unroll
            for (int i = 0; i < 4; i++)
                #pragma unroll
                for (int j = 0; j < 4; j++)
                    acc[i][j] += ar[i] * br[j];
        }
        __syncthreads();
    }

    #pragma unroll
    for (int i = 0; i < 4; i++) {
        int m = m0 + ty * 4 + i;
        #pragma unroll
        for (int j = 0; j < 4; j++) {
            int n = n0 + tx * 4 + j;
            float val = acc[i][j] + bias[n];
            if (HEADS) {
                int b = m >> 11;         // /S
                int s = m & (SS - 1);
                int h = n >> 6;          // /HD
                int hd = n & (HD - 1);
                out[((((size_t)b * HH + h) * SS + s) << 6) + hd] = val;
            } else {
                out[(size_t)m * N + n] = val;
            }
        }
    }
}

// ---------------- attention: online softmax, 64-row q tile ----------------
// grid: (S/64, H, B), block 256
// dyn smem: Qs[64*65] Ks[64*65] Ps[64*65] Vs[64*64] Bs[64*64]
__global__ __launch_bounds__(256)
void attn_kernel(const float* __restrict__ Q, const float* __restrict__ K,
                 const float* __restrict__ V, const float* __restrict__ bias,
                 const float* __restrict__ mask, float* __restrict__ ctx)
{
    extern __shared__ float sm[];
    float* Qs = sm;                // stride 65
    float* Ks = Qs + 64 * 65;      // stride 65
    float* Ps = Ks + 64 * 65;      // stride 65
    float* Vs = Ps + 64 * 65;      // stride 64
    float* Bs = Vs + 64 * 64;      // stride 64

    const int tid = threadIdx.x;
    const int tx = tid & 15, ty = tid >> 4;
    const int q0 = blockIdx.x * 64;
    const int h  = blockIdx.y;
    const int b  = blockIdx.z;

    const float* qb = Q + (((size_t)b * HH + h) * SS + q0) * HD;
    const float* kb = K + (((size_t)b * HH + h) * SS) * HD;
    const float* vb = V + (((size_t)b * HH + h) * SS) * HD;
    const float* bb = bias + (size_t)h * SS * SS + (size_t)q0 * SS;
    const float* mk = mask + (size_t)b * SS;

    // load Q tile
    for (int e = tid; e < 64 * 64; e += 256) {
        int r = e >> 6, c = e & 63;
        Qs[r * 65 + c] = qb[e];
    }

    const int rr = ty * 4, cc = tx * 4;
    float m_i[4], l_i[4], acc[4][4] = {};
    #pragma unroll
    for (int i = 0; i < 4; i++) { m_i[i] = -1e30f; l_i[i] = 0.f; }

    for (int kt = 0; kt < SS; kt += 64) {
        // load K, V, bias tiles
        for (int e = tid; e < 64 * 64; e += 256) {
            int r = e >> 6, c = e & 63;
            Ks[r * 65 + c] = kb[(size_t)(kt + r) * HD + c];
            Vs[r * 64 + c] = vb[(size_t)(kt + r) * HD + c];
            Bs[r * 64 + c] = bb[(size_t)r * SS + kt + c];
        }
        __syncthreads();   // also covers initial Q load

        float mask4[4];
        #pragma unroll
        for (int j = 0; j < 4; j++) mask4[j] = mk[kt + cc + j];

        // scores
        float s[4][4];
        #pragma unroll
        for (int i = 0; i < 4; i++)
            #pragma unroll
            for (int j = 0; j < 4; j++) s[i][j] = 0.f;

        #pragma unroll 16
        for (int kk = 0; kk < 64; kk++) {
            float qv[4], kv[4];
            #pragma unroll
            for (int i = 0; i < 4; i++) qv[i] = Qs[(rr + i) * 65 + kk];
            #pragma unroll
            for (int j = 0; j < 4; j++) kv[j] = Ks[(cc + j) * 65 + kk];
            #pragma unroll
            for (int i = 0; i < 4; i++)
                #pragma unroll
                for (int j = 0; j < 4; j++)
                    s[i][j] += qv[i] * kv[j];
        }

        // scale + bias + mask, online softmax per row
        #pragma unroll
        for (int i = 0; i < 4; i++) {
            #pragma unroll
            for (int j = 0; j < 4; j++)
                s[i][j] = s[i][j] * 0.125f + Bs[(rr + i) * 64 + cc + j] + mask4[j];

            float tmax = fmaxf(fmaxf(s[i][0], s[i][1]), fmaxf(s[i][2], s[i][3]));
            #pragma unroll
            for (int off = 8; off >= 1; off >>= 1)
                tmax = fmaxf(tmax, __shfl_xor_sync(0xffffffffu, tmax, off));

            float mnew = fmaxf(m_i[i], tmax);
            float scale = __expf(m_i[i] - mnew);
            float rsum = 0.f;
            #pragma unroll
            for (int j = 0; j < 4; j++) {
                float p = __expf(s[i][j] - mnew);
                Ps[(rr + i) * 65 + cc + j] = p;
                rsum += p;
            }
            #pragma unroll
            for (int off = 8; off >= 1; off >>= 1)
                rsum += __shfl_xor_sync(0xffffffffu, rsum, off);

            l_i[i] = l_i[i] * scale + rsum;
            m_i[i] = mnew;
            #pragma unroll
            for (int j = 0; j < 4; j++) acc[i][j] *= scale;
        }
        __syncthreads();   // P visible to all

        // O += P @ V
        #pragma unroll 16
        for (int kk = 0; kk < 64; kk++) {
            float pv[4];
            #pragma unroll
            for (int i = 0; i < 4; i++) pv[i] = Ps[(rr + i) * 65 + kk];
            float4 v4 = *(const float4*)&Vs[kk * 64 + cc];
            float vv[4] = {v4.x, v4.y, v4.z, v4.w};
            #pragma unroll
            for (int i = 0; i < 4; i++)
                #pragma unroll
                for (int j = 0; j < 4; j++)
                    acc[i][j] += pv[i] * vv[j];
        }
        __syncthreads();   // before next tile overwrites Ks/Vs/Bs
    }

    // normalize + write ctx in [B,S,D]
    #pragma unroll
    for (int i = 0; i < 4; i++) {
        float inv = 1.f / l_i[i];
        #pragma unroll
        for (int j = 0; j < 4; j++) {
            ctx[((size_t)b * SS + q0 + rr + i) * DD + h * HD + cc + j] = acc[i][j] * inv;
        }
    }
}

// ---------------- launch ----------------
extern "C" void kernel_launch(void* const* d_in, const int* in_sizes, int n_in,
                              void* d_out, int out_size)
{
    const float* hidden = (const float*)d_in[0];
    const float* amask  = (const float*)d_in[1];
    const float* pbias  = (const float*)d_in[2];
    const float* Wq = (const float*)d_in[3];
    const float* bq = (const float*)d_in[4];
    const float* Wk = (const float*)d_in[5];
    const float* bk = (const float*)d_in[6];
    const float* Wv = (const float*)d_in[7];
    const float* bv = (const float*)d_in[8];
    const float* Wo = (const float*)d_in[9];
    const float* bo = (const float*)d_in[10];
    float* out = (float*)d_out;

    float *pq, *pk, *pv, *pctx;
    cudaGetSymbolAddress((void**)&pq,  g_q);
    cudaGetSymbolAddress((void**)&pk,  g_k);
    cudaGetSymbolAddress((void**)&pv,  g_v);
    cudaGetSymbolAddress((void**)&pctx, g_ctx);

    const int smem_attn = (3 * 64 * 65 + 2 * 64 * 64) * sizeof(float);  // 82688
    cudaFuncSetAttribute(attn_kernel, cudaFuncAttributeMaxDynamicSharedMemorySize, smem_attn);

    dim3 blk(256);
    dim3 gproj(DD / 64, MROWS / 64);   // (16, 64)

    gemm64<1><<<gproj, blk>>>(hidden, Wq, bq, pq, MROWS, DD, DD);
    gemm64<1><<<gproj, blk>>>(hidden, Wk, bk, pk, MROWS, DD, DD);
    gemm64<1><<<gproj, blk>>>(hidden, Wv, bv, pv, MROWS, DD, DD);

    dim3 gattn(SS / 64, HH, BB);       // (32, 16, 2)
    attn_kernel<<<gattn, blk, smem_attn>>>(pq, pk, pv, pbias, amask, pctx);

    gemm64<0><<<gproj, blk>>>(pctx, Wo, bo, out, MROWS, DD, DD);
}

// round 15
// speedup vs baseline: 2.0670x; 2.0670x over previous
#include <cuda_runtime.h>
#include <cuda_bf16.h>
#include <stdint.h>

#define BB 2
#define SS 2048
#define DD 1024
#define HH 16
#define HD 64
#define MROWS (BB*SS)   // 4096
#define KU32 (DD/2)     // 512 u32 per row of split matrices

// ================= helpers =================
__device__ __forceinline__ uint32_t smem_u32(const void* p) {
    uint32_t a;
    asm("{ .reg .u64 t; cvta.to.shared.u64 t, %1; cvt.u32.u64 %0, t; }" : "=r"(a) : "l"(p));
    return a;
}
__device__ __forceinline__ void ldsm4(uint32_t* r, uint32_t a) {
    asm volatile("ldmatrix.sync.aligned.m8n8.x4.shared.b16 {%0,%1,%2,%3}, [%4];"
        : "=r"(r[0]), "=r"(r[1]), "=r"(r[2]), "=r"(r[3]) : "r"(a));
}
__device__ __forceinline__ void ldsm4t(uint32_t* r, uint32_t a) {
    asm volatile("ldmatrix.sync.aligned.m8n8.x4.trans.shared.b16 {%0,%1,%2,%3}, [%4];"
        : "=r"(r[0]), "=r"(r[1]), "=r"(r[2]), "=r"(r[3]) : "r"(a));
}
__device__ __forceinline__ void mma_bf16(float* c, const uint32_t* a, uint32_t b0, uint32_t b1) {
    asm volatile("mma.sync.aligned.m16n8k16.row.col.f32.bf16.bf16.f32 "
        "{%0,%1,%2,%3},{%4,%5,%6,%7},{%8,%9},{%0,%1,%2,%3};"
        : "+f"(c[0]), "+f"(c[1]), "+f"(c[2]), "+f"(c[3])
        : "r"(a[0]), "r"(a[1]), "r"(a[2]), "r"(a[3]), "r"(b0), "r"(b1));
}
__device__ __forceinline__ void split2(float x, __nv_bfloat16& hi, __nv_bfloat16& lo) {
    hi = __float2bfloat16(x);
    lo = __float2bfloat16(x - __bfloat162float(hi));
}
__device__ __forceinline__ uint32_t pack2(__nv_bfloat16 a, __nv_bfloat16 b) {
    __nv_bfloat162 t; t.x = a; t.y = b;
    return *(uint32_t*)&t;
}
__device__ __forceinline__ void splitpack(float v0, float v1, uint32_t& hi, uint32_t& lo) {
    __nv_bfloat16 h0, l0, h1, l1; split2(v0, h0, l0); split2(v1, h1, l1);
    hi = pack2(h0, h1); lo = pack2(l0, l1);
}

// ================= device scratch =================
__device__ __align__(16) __nv_bfloat16 g_hhi[MROWS * DD], g_hlo[MROWS * DD];      // hidden split [4096][1024]
__device__ __align__(16) __nv_bfloat16 g_wthi[4 * DD * DD], g_wtlo[4 * DD * DD];  // W^T split (q,k,v,o) [N][K]
__device__ __align__(16) __nv_bfloat16 g_qhi[BB*HH*SS*HD], g_qlo[BB*HH*SS*HD];    // [B,H,S,HD]
__device__ __align__(16) __nv_bfloat16 g_khi[BB*HH*SS*HD], g_klo[BB*HH*SS*HD];
__device__ __align__(16) __nv_bfloat16 g_vhi[BB*HH*SS*HD], g_vlo[BB*HH*SS*HD];
__device__ __align__(16) __nv_bfloat16 g_cthi[MROWS * DD], g_ctlo[MROWS * DD];    // ctx split [4096][1024]

// ================= pre-pass =================
__global__ __launch_bounds__(256) void split_f32(const float* __restrict__ src,
                                                 __nv_bfloat16* __restrict__ hi,
                                                 __nv_bfloat16* __restrict__ lo, int n) {
    int i = blockIdx.x * 256 + threadIdx.x;
    if (i < n) { __nv_bfloat16 h, l; split2(src[i], h, l); hi[i] = h; lo[i] = l; }
}

__global__ __launch_bounds__(256) void transpose_split(const float* __restrict__ W,
                                                       __nv_bfloat16* __restrict__ Thi,
                                                       __nv_bfloat16* __restrict__ Tlo) {
    __shared__ float t[32][33];
    int tx = threadIdx.x, ty = threadIdx.y;          // (32, 8)
    int n0 = blockIdx.x * 32, k0 = blockIdx.y * 32;
    #pragma unroll
    for (int i = 0; i < 4; i++)
        t[ty + i * 8][tx] = W[(size_t)(k0 + ty + i * 8) * DD + n0 + tx];
    __syncthreads();
    #pragma unroll
    for (int i = 0; i < 4; i++) {
        float x = t[tx][ty + i * 8];
        __nv_bfloat16 h, l; split2(x, h, l);
        size_t o = (size_t)(n0 + ty + i * 8) * DD + k0 + tx;
        Thi[o] = h; Tlo[o] = l;
    }
}

// ================= projection GEMM (mma.sync, split-bf16 3-term) =================
// out[4096,1024] = A @ Wt^T + bias. BM=128, BN=128, BK=64, 8 warps (2 M x 4 N), warp 64x32.
// MODE 0: split-packed write to (Dhi, Dlo) in [B,H,S,HD]; MODE 1: fp32 flat to outf.
#define PJ_ROWU 36              // u32 per smem row (64 bf16 + 8 pad)
#define PJ_A_HI 0
#define PJ_A_LO (128 * PJ_ROWU)
#define PJ_B_HI (2 * 128 * PJ_ROWU)
#define PJ_B_LO (3 * 128 * PJ_ROWU)
#define PJ_SMEM (4 * 128 * PJ_ROWU * 4)   // bytes = 73728

template<int MODE>
__global__ __launch_bounds__(256) void proj_mma(
    const uint32_t* __restrict__ Ahi, const uint32_t* __restrict__ Alo,
    const uint32_t* __restrict__ Bhi, const uint32_t* __restrict__ Blo,
    const float* __restrict__ bias,
    uint32_t* __restrict__ Dhi, uint32_t* __restrict__ Dlo, float* __restrict__ outf)
{
    extern __shared__ uint32_t sm32[];
    const uint32_t sbase = smem_u32(sm32);
    const int tid = threadIdx.x, lane = tid & 31, warp = tid >> 5;
    const int wm = warp >> 2, wn = warp & 3;
    const int m0 = blockIdx.y * 128, n0 = blockIdx.x * 128;

    float acc[4][4][4] = {};

    const uint32_t aSel[3] = { sbase + PJ_A_HI * 4, sbase + PJ_A_HI * 4, sbase + PJ_A_LO * 4 };
    const uint32_t bSel[3] = { sbase + PJ_B_HI * 4, sbase + PJ_B_LO * 4, sbase + PJ_B_HI * 4 };

    for (int k0 = 0; k0 < KU32; k0 += 32) {
        __syncthreads();
        #pragma unroll
        for (int i = 0; i < 16; i++) {
            int idx = tid + i * 256;           // 0..4095
            int r = idx >> 5, c = idx & 31;
            sm32[PJ_A_HI + r * PJ_ROWU + c] = Ahi[(size_t)(m0 + r) * KU32 + k0 + c];
            sm32[PJ_A_LO + r * PJ_ROWU + c] = Alo[(size_t)(m0 + r) * KU32 + k0 + c];
            sm32[PJ_B_HI + r * PJ_ROWU + c] = Bhi[(size_t)(n0 + r) * KU32 + k0 + c];
            sm32[PJ_B_LO + r * PJ_ROWU + c] = Blo[(size_t)(n0 + r) * KU32 + k0 + c];
        }
        __syncthreads();

        #pragma unroll
        for (int p = 0; p < 3; p++) {
            uint32_t aB = aSel[p] + (wm * 64 + (lane & 15)) * (PJ_ROWU * 4) + (lane >> 4) * 16;
            uint32_t bB = bSel[p] + (wn * 32 + (lane & 15)) * (PJ_ROWU * 4) + (lane >> 4) * 16;
            #pragma unroll
            for (int ks = 0; ks < 4; ks++) {
                uint32_t af[4][4], bf[2][4];
                #pragma unroll
                for (int mf = 0; mf < 4; mf++) ldsm4(af[mf], aB + mf * 16 * (PJ_ROWU * 4) + ks * 32);
                #pragma unroll
                for (int np = 0; np < 2; np++) ldsm4(bf[np], bB + np * 16 * (PJ_ROWU * 4) + ks * 32);
                #pragma unroll
                for (int mf = 0; mf < 4; mf++)
                    #pragma unroll
                    for (int nf = 0; nf < 4; nf++) {
                        const uint32_t* bb = bf[nf >> 1];
                        uint32_t b0 = (nf & 1) ? bb[1] : bb[0];
                        uint32_t b1 = (nf & 1) ? bb[3] : bb[2];
                        mma_bf16(acc[mf][nf], af[mf], b0, b1);
                    }
            }
        }
    }

    const int mrow = m0 + wm * 64 + (lane >> 2);
    const int ncol = n0 + wn * 32 + (lane & 3) * 2;
    #pragma unroll
    for (int mf = 0; mf < 4; mf++)
        #pragma unroll
        for (int half = 0; half < 2; half++) {
            int m = mrow + mf * 16 + half * 8;
            #pragma unroll
            for (int nf = 0; nf < 4; nf++) {
                int n = ncol + nf * 8;
                float v0 = acc[mf][nf][half * 2 + 0] + bias[n];
                float v1 = acc[mf][nf][half * 2 + 1] + bias[n + 1];
                if (MODE == 0) {
                    int b = m >> 11, s = m & (SS - 1), h = n >> 6, hd = n & 63;
                    size_t o = ((size_t)((b << 4) | h) * SS + s) * (HD / 2) + (hd >> 1);
                    uint32_t hi, lo; splitpack(v0, v1, hi, lo);
                    Dhi[o] = hi; Dlo[o] = lo;
                } else {
                    float2 v = make_float2(v0, v1);
                    *(float2*)&outf[(size_t)m * DD + n] = v;
                }
            }
        }
}

// ================= attention (mma.sync, split-bf16 3-term, no-max softmax) =================
// grid (S/128, H, B), 256 threads, 8 warps (4 M x 2 N), warp 32q x 32(k|hd).
#define AT_ROWU 36
#define AT_QH 0
#define AT_QL (128 * AT_ROWU)
#define AT_KH (2 * 128 * AT_ROWU)
#define AT_KL (AT_KH + 64 * AT_ROWU)
#define AT_VH (AT_KH + 2 * 64 * AT_ROWU)
#define AT_VL (AT_KH + 3 * 64 * AT_ROWU)
#define AT_PH (AT_KH + 4 * 64 * AT_ROWU)
#define AT_PL (AT_PH + 128 * AT_ROWU)
#define AT_LS (AT_PH + 2 * 128 * AT_ROWU)
#define AT_SMEM ((AT_LS + 128) * 4)       // bytes = 111616

__global__ __launch_bounds__(256) void attn_mma(const float* __restrict__ bias,
                                                const float* __restrict__ mask)
{
    extern __shared__ uint32_t sm32[];
    const uint32_t sbase = smem_u32(sm32);
    const int tid = threadIdx.x, lane = tid & 31, warp = tid >> 5;
    const int wm = warp >> 1, wn = warp & 1;
    const int q0 = blockIdx.x * 128, h = blockIdx.y, b = blockIdx.z;
    const size_t bh = (size_t)(b * HH + h);

    const uint32_t* qh = (const uint32_t*)g_qhi; const uint32_t* ql = (const uint32_t*)g_qlo;
    const uint32_t* kh = (const uint32_t*)g_khi; const uint32_t* kl = (const uint32_t*)g_klo;
    const uint32_t* vh = (const uint32_t*)g_vhi; const uint32_t* vl = (const uint32_t*)g_vlo;

    if (tid < 128) ((float*)&sm32[AT_LS])[tid] = 0.f;

    // Q tile [128][64] hi/lo
    #pragma unroll
    for (int i = 0; i < 16; i++) {
        int idx = tid + i * 256;
        int r = idx >> 5, c = idx & 31;
        sm32[AT_QH + r * AT_ROWU + c] = qh[(bh * SS + q0 + r) * 32 + c];
        sm32[AT_QL + r * AT_ROWU + c] = ql[(bh * SS + q0 + r) * 32 + c];
    }

    const uint32_t qSel[3] = { sbase + AT_QH * 4, sbase + AT_QH * 4, sbase + AT_QL * 4 };
    const uint32_t kSel[3] = { sbase + AT_KH * 4, sbase + AT_KL * 4, sbase + AT_KH * 4 };
    const uint32_t pSel[3] = { sbase + AT_PH * 4, sbase + AT_PH * 4, sbase + AT_PL * 4 };
    const uint32_t vSel[3] = { sbase + AT_VH * 4, sbase + AT_VL * 4, sbase + AT_VH * 4 };

    float oa[2][4][4] = {};
    float lp[2][2] = {};

    const int qrow = wm * 32 + (lane >> 2);           // local q row base
    const float* mrow = mask + (size_t)b * SS;

    for (int kt = 0; kt < SS; kt += 64) {
        __syncthreads();                               // guards Q load + prior chunk reads
        #pragma unroll
        for (int i = 0; i < 8; i++) {
            int idx = tid + i * 256;                   // 0..2047
            int r = idx >> 5, c = idx & 31;
            size_t g = (bh * SS + kt + r) * 32 + c;
            sm32[AT_KH + r * AT_ROWU + c] = kh[g];
            sm32[AT_KL + r * AT_ROWU + c] = kl[g];
            sm32[AT_VH + r * AT_ROWU + c] = vh[g];
            sm32[AT_VL + r * AT_ROWU + c] = vl[g];
        }
        __syncthreads();

        // ---- S = Q @ K^T (3-term) ----
        float sc[2][4][4] = {};
        #pragma unroll
        for (int p = 0; p < 3; p++) {
            uint32_t aB = qSel[p] + (wm * 32 + (lane & 15)) * (AT_ROWU * 4) + (lane >> 4) * 16;
            uint32_t bB = kSel[p] + (wn * 32 + (lane & 15)) * (AT_ROWU * 4) + (lane >> 4) * 16;
            #pragma unroll
            for (int ks = 0; ks < 4; ks++) {
                uint32_t af[2][4], bf[2][4];
                #pragma unroll
                for (int mf = 0; mf < 2; mf++) ldsm4(af[mf], aB + mf * 16 * (AT_ROWU * 4) + ks * 32);
                #pragma unroll
                for (int np = 0; np < 2; np++) ldsm4(bf[np], bB + np * 16 * (AT_ROWU * 4) + ks * 32);
                #pragma unroll
                for (int mf = 0; mf < 2; mf++)
                    #pragma unroll
                    for (int nf = 0; nf < 4; nf++) {
                        const uint32_t* bb = bf[nf >> 1];
                        uint32_t b0 = (nf & 1) ? bb[1] : bb[0];
                        uint32_t b1 = (nf & 1) ? bb[3] : bb[2];
                        mma_bf16(sc[mf][nf], af[mf], b0, b1);
                    }
            }
        }

        // ---- bias + mask + exp, pack split P into smem ----
        #pragma unroll
        for (int mf = 0; mf < 2; mf++)
            #pragma unroll
            for (int half = 0; half < 2; half++) {
                int rloc = qrow + mf * 16 + half * 8;
                const float* brow = bias + ((size_t)h * SS + (q0 + rloc)) * SS + kt;
                float lsum = 0.f;
                #pragma unroll
                for (int nf = 0; nf < 4; nf++) {
                    int kc = wn * 32 + nf * 8 + (lane & 3) * 2;
                    float s0 = fmaf(sc[mf][nf][half * 2 + 0], 0.125f, brow[kc]     + mrow[kt + kc]);
                    float s1 = fmaf(sc[mf][nf][half * 2 + 1], 0.125f, brow[kc + 1] + mrow[kt + kc + 1]);
                    float p0 = __expf(s0), p1 = __expf(s1);
                    lsum += p0 + p1;
                    uint32_t hi, lo; splitpack(p0, p1, hi, lo);
                    int pidx = rloc * AT_ROWU + (kc >> 1);
                    sm32[AT_PH + pidx] = hi;
                    sm32[AT_PL + pidx] = lo;
                }
                lp[mf][half] += lsum;
            }
        __syncthreads();

        // ---- O += P @ V (V via ldmatrix.trans) (3-term) ----
        #pragma unroll
        for (int p = 0; p < 3; p++) {
            uint32_t aB = pSel[p] + (wm * 32 + (lane & 15)) * (AT_ROWU * 4) + (lane >> 4) * 16;
            uint32_t bB = vSel[p] + (lane & 15) * (AT_ROWU * 4) + wn * 64 + (lane >> 4) * 16;
            #pragma unroll
            for (int ks = 0; ks < 4; ks++) {
                uint32_t af[2][4], bf[2][4];
                #pragma unroll
                for (int mf = 0; mf < 2; mf++) ldsm4(af[mf], aB + mf * 16 * (AT_ROWU * 4) + ks * 32);
                #pragma unroll
                for (int np = 0; np < 2; np++) ldsm4t(bf[np], bB + ks * 16 * (AT_ROWU * 4) + np * 32);
                #pragma unroll
                for (int mf = 0; mf < 2; mf++)
                    #pragma unroll
                    for (int nf = 0; nf < 4; nf++) {
                        const uint32_t* bb = bf[nf >> 1];
                        uint32_t b0 = (nf & 1) ? bb[2] : bb[0];
                        uint32_t b1 = (nf & 1) ? bb[3] : bb[1];
                        mma_bf16(oa[mf][nf], af[mf], b0, b1);
                    }
            }
        }
    }

    // ---- row sums: reduce over lane%4 group, then across warps via smem atomics ----
    float* lsf = (float*)&sm32[AT_LS];
    #pragma unroll
    for (int mf = 0; mf < 2; mf++)
        #pragma unroll
        for (int half = 0; half < 2; half++) {
            float v = lp[mf][half];
            v += __shfl_xor_sync(0xffffffffu, v, 1);
            v += __shfl_xor_sync(0xffffffffu, v, 2);
            if ((lane & 3) == 0)
                atomicAdd(&lsf[qrow + mf * 16 + half * 8], v);
        }
    __syncthreads();

    // ---- normalize + split-pack ctx ----
    uint32_t* ch = (uint32_t*)g_cthi;
    uint32_t* cl = (uint32_t*)g_ctlo;
    #pragma unroll
    for (int mf = 0; mf < 2; mf++)
        #pragma unroll
        for (int half = 0; half < 2; half++) {
            int rloc = qrow + mf * 16 + half * 8;
            float inv = 1.f / lsf[rloc];
            #pragma unroll
            for (int nf = 0; nf < 4; nf++) {
                int hd = wn * 32 + nf * 8 + (lane & 3) * 2;
                float v0 = oa[mf][nf][half * 2 + 0] * inv;
                float v1 = oa[mf][nf][half * 2 + 1] * inv;
                uint32_t hi, lo; splitpack(v0, v1, hi, lo);
                size_t o = ((size_t)(b * SS + q0 + rloc) * DD + h * HD + hd) >> 1;
                ch[o] = hi; cl[o] = lo;
            }
        }
}

// ================= launch =================
extern "C" void kernel_launch(void* const* d_in, const int* in_sizes, int n_in,
                              void* d_out, int out_size)
{
    const float* hidden = (const float*)d_in[0];
    const float* amask  = (const float*)d_in[1];
    const float* pbias  = (const float*)d_in[2];
    const float* Wq = (const float*)d_in[3];
    const float* bq = (const float*)d_in[4];
    const float* Wk = (const float*)d_in[5];
    const float* bk = (const float*)d_in[6];
    const float* Wv = (const float*)d_in[7];
    const float* bv = (const float*)d_in[8];
    const float* Wo = (const float*)d_in[9];
    const float* bo = (const float*)d_in[10];
    float* out = (float*)d_out;

    __nv_bfloat16 *hhi, *hlo, *wthi, *wtlo, *cthi, *ctlo, *qhi, *qlo, *khi, *klo, *vhi, *vlo;
    cudaGetSymbolAddress((void**)&hhi,  g_hhi);
    cudaGetSymbolAddress((void**)&hlo,  g_hlo);
    cudaGetSymbolAddress((void**)&wthi, g_wthi);
    cudaGetSymbolAddress((void**)&wtlo, g_wtlo);
    cudaGetSymbolAddress((void**)&cthi, g_cthi);
    cudaGetSymbolAddress((void**)&ctlo, g_ctlo);
    cudaGetSymbolAddress((void**)&qhi,  g_qhi);
    cudaGetSymbolAddress((void**)&qlo,  g_qlo);
    cudaGetSymbolAddress((void**)&khi,  g_khi);
    cudaGetSymbolAddress((void**)&klo,  g_klo);
    cudaGetSymbolAddress((void**)&vhi,  g_vhi);
    cudaGetSymbolAddress((void**)&vlo,  g_vlo);

    cudaFuncSetAttribute(proj_mma<0>, cudaFuncAttributeMaxDynamicSharedMemorySize, PJ_SMEM);
    cudaFuncSetAttribute(proj_mma<1>, cudaFuncAttributeMaxDynamicSharedMemorySize, PJ_SMEM);
    cudaFuncSetAttribute(attn_mma,    cudaFuncAttributeMaxDynamicSharedMemorySize, AT_SMEM);

    split_f32<<<(MROWS * DD + 255) / 256, 256>>>(hidden, hhi, hlo, MROWS * DD);
    dim3 tb(32, 8), tg(DD / 32, DD / 32);
    transpose_split<<<tg, tb>>>(Wq, wthi + 0 * (size_t)DD * DD, wtlo + 0 * (size_t)DD * DD);
    transpose_split<<<tg, tb>>>(Wk, wthi + 1 * (size_t)DD * DD, wtlo + 1 * (size_t)DD * DD);
    transpose_split<<<tg, tb>>>(Wv, wthi + 2 * (size_t)DD * DD, wtlo + 2 * (size_t)DD * DD);
    transpose_split<<<tg, tb>>>(Wo, wthi + 3 * (size_t)DD * DD, wtlo + 3 * (size_t)DD * DD);

    dim3 pg(DD / 128, MROWS / 128);    // (8, 32)
    proj_mma<0><<<pg, 256, PJ_SMEM>>>((const uint32_t*)hhi, (const uint32_t*)hlo,
        (const uint32_t*)(wthi + 0 * (size_t)DD * DD), (const uint32_t*)(wtlo + 0 * (size_t)DD * DD),
        bq, (uint32_t*)qhi, (uint32_t*)qlo, nullptr);
    proj_mma<0><<<pg, 256, PJ_SMEM>>>((const uint32_t*)hhi, (const uint32_t*)hlo,
        (const uint32_t*)(wthi + 1 * (size_t)DD * DD), (const uint32_t*)(wtlo + 1 * (size_t)DD * DD),
        bk, (uint32_t*)khi, (uint32_t*)klo, nullptr);
    proj_mma<0><<<pg, 256, PJ_SMEM>>>((const uint32_t*)hhi, (const uint32_t*)hlo,
        (const uint32_t*)(wthi + 2 * (size_t)DD * DD), (const uint32_t*)(wtlo + 2 * (size_t)DD * DD),
        bv, (uint32_t*)vhi, (uint32_t*)vlo, nullptr);

    dim3 ag(SS / 128, HH, BB);         // (16, 16, 2)
    attn_mma<<<ag, 256, AT_SMEM>>>(pbias, amask);

    proj_mma<1><<<pg, 256, PJ_SMEM>>>((const uint32_t*)cthi, (const uint32_t*)ctlo,
        (const uint32_t*)(wthi + 3 * (size_t)DD * DD), (const uint32_t*)(wtlo + 3 * (size_t)DD * DD),
        bo, nullptr, nullptr, out);
}